// round 1
// baseline (speedup 1.0000x reference)
#include <cuda_runtime.h>
#include <cuda_bf16.h>

#define HW 256
#define NTHREADS 256
#define TILE 8
#define TPAD 9
#define PLANE (HW * HW)

// Order-independent float max via integer atomics.
// Requires destination pre-initialized to 0xFFFFFFFF (NaN bits: int -1, uint max),
// which loses to any finite float under this scheme.
__device__ __forceinline__ void atomic_max_float(float* p, float v) {
    int iv = __float_as_int(v);
    if (iv >= 0) {
        atomicMax((int*)p, iv);               // positive floats: int order == float order
    } else {
        atomicMin((unsigned int*)p, (unsigned int)iv); // negative floats: reversed in uint order
    }
}

__global__ __launch_bounds__(NTHREADS) void spn_kernel(
    const float* __restrict__ x,
    const float* __restrict__ mask,
    float* __restrict__ out)
{
    extern __shared__ float sm[];
    float* sp = sm;                    // (1-a-b-c)*x   [HW][TPAD] or [TILE][HW]
    float* sa = sp + HW * TPAD;
    float* sb = sa + HW * TPAD;
    float* sc = sb + HW * TPAD;
    float* so = sc + HW * TPAD;        // horizontal output staging tile
    float* hb = so + HW * TPAD;        // 2 x (HW+2) zero-padded h double buffer

    const int k   = threadIdx.x;
    const int blk = blockIdx.x;
    const int dir = blk >> 7;          // 0: h-fwd, 1: h-rev, 2: v-fwd, 3: v-rev
    const int bc  = blk & 127;         // b*32 + c
    const int b   = bc >> 5;
    const int c   = bc & 31;
    const bool horiz = (dir < 2);
    const bool rev   = (dir & 1);

    const float* mb  = mask + (size_t)bc * PLANE;
    const float* g1b = x + (size_t)(b * 384 + (3 * dir + 0) * 32 + c) * PLANE;
    const float* g2b = x + (size_t)(b * 384 + (3 * dir + 1) * 32 + c) * PLANE;
    const float* g3b = x + (size_t)(b * 384 + (3 * dir + 2) * 32 + c) * PLANE;
    float* ob = out + (size_t)bc * PLANE;

    // zero both h buffers (incl. boundary pads, which are never written again)
    for (int i = k; i < 2 * (HW + 2); i += NTHREADS) hb[i] = 0.f;
    float* cur = hb;
    float* nxt = hb + (HW + 2);
    float hreg = 0.f;                  // this thread's own h (== cur[k+1])
    __syncthreads();

    for (int tile = 0; tile < HW / TILE; ++tile) {
        // base0: lowest memory index (w for horiz, h for vert) covered by this tile
        const int base0 = rev ? (HW - TILE - TILE * tile) : (TILE * tile);

        // ---- load + normalize one tile of 8 scan-steps into smem (coalesced) ----
        if (horiz) {
            // tile = 256 rows x 8 cols; warp covers 4 rows x 8 consecutive floats (32B each)
            #pragma unroll
            for (int j = 0; j < (HW * TILE) / NTHREADS; ++j) {
                int i = k + j * NTHREADS;
                int row = i >> 3, col = i & 7;
                int g = row * HW + base0 + col;
                float m  = mb[g];
                float G1 = g1b[g], G2 = g2b[g], G3 = g3b[g];
                float s = fabsf(G1) + fabsf(G2) + fabsf(G3) + 1e-7f;
                float r = (s >= 1.f) ? __fdividef(1.f, s) : 1.f;
                float a = G1 * r, bb = G2 * r, cc = G3 * r;
                int t = row * TPAD + col;
                sp[t] = (1.f - a - bb - cc) * m;
                sa[t] = a; sb[t] = bb; sc[t] = cc;
            }
        } else {
            // tile = 8 rows x 256 cols; fully coalesced flat copy
            #pragma unroll
            for (int j = 0; j < (HW * TILE) / NTHREADS; ++j) {
                int i = k + j * NTHREADS;
                int g = base0 * HW + i;
                float m  = mb[g];
                float G1 = g1b[g], G2 = g2b[g], G3 = g3b[g];
                float s = fabsf(G1) + fabsf(G2) + fabsf(G3) + 1e-7f;
                float r = (s >= 1.f) ? __fdividef(1.f, s) : 1.f;
                float a = G1 * r, bb = G2 * r, cc = G3 * r;
                sp[i] = (1.f - a - bb - cc) * m;
                sa[i] = a; sb[i] = bb; sc[i] = cc;
            }
        }
        __syncthreads();

        // ---- 8 sequential scan steps ----
        #pragma unroll
        for (int st = 0; st < TILE; ++st) {
            int L = rev ? (TILE - 1 - st) : st;            // position within tile, memory order
            int idx = horiz ? (k * TPAD + L) : (L * HW + k);
            float hm = cur[k];                             // h_prev(k-1)  (pad -> 0)
            float hp = cur[k + 2];                         // h_prev(k+1)  (pad -> 0)
            float hn = fmaf(sa[idx], hm, sp[idx]);
            hn = fmaf(sb[idx], hreg, hn);
            hn = fmaf(sc[idx], hp, hn);
            hreg = hn;
            nxt[k + 1] = hn;
            if (horiz) {
                so[idx] = hn;                              // stage for coalesced flush
            } else {
                atomic_max_float(ob + (base0 + L) * HW + k, hn);  // coalesced in k
            }
            __syncthreads();
            float* t = cur; cur = nxt; nxt = t;
        }

        // ---- flush horizontal output tile, coalesced ----
        if (horiz) {
            #pragma unroll
            for (int j = 0; j < (HW * TILE) / NTHREADS; ++j) {
                int i = k + j * NTHREADS;
                int row = i >> 3, col = i & 7;
                atomic_max_float(ob + row * HW + base0 + col, so[row * TPAD + col]);
            }
            // no extra sync needed: the __syncthreads after the next tile's load
            // orders these reads of `so` before the next tile's step writes.
        }
    }
}

extern "C" void kernel_launch(void* const* d_in, const int* in_sizes, int n_in,
                              void* d_out, int out_size) {
    const float* x    = (const float*)d_in[0];
    const float* mask = (const float*)d_in[1];
    // defensive: x is 12x larger than mask
    if (n_in >= 2 && in_sizes[0] < in_sizes[1]) {
        x    = (const float*)d_in[1];
        mask = (const float*)d_in[0];
    }
    // init out to 0xFFFFFFFF (loses to everything under the int/uint atomic-max scheme)
    cudaMemsetAsync(d_out, 0xFF, (size_t)out_size * sizeof(float));

    size_t smem = (size_t)(5 * HW * TPAD + 2 * (HW + 2)) * sizeof(float);  // 48,144 B
    spn_kernel<<<512, NTHREADS, smem>>>(x, mask, (float*)d_out);
}